// round 4
// baseline (speedup 1.0000x reference)
#include <cuda_runtime.h>
#include <cuda_bf16.h>
#include <math.h>

#define B_ 64
#define S_ 512
#define I_ 256
#define H_ 1024
#define O_ 128

// Scratch (static device globals — no dynamic allocation).
__device__ __nv_bfloat16 g_buf[(size_t)B_ * S_ * H_];          // (1-beta)*(ff + b_in + b_rec), bf16, 67MB
__device__ unsigned      spk_buf[(size_t)B_ * S_ * (H_ / 32)]; // spike bitmasks per (b,t), 4MB
__device__ float         s1_buf[H_];                           // 1 - beta
__device__ float         s2_buf[H_];                           // b_in + b_rec

__device__ __forceinline__ float sigmoidf_(float x) { return 1.f / (1.f + expf(-x)); }

// ---------------------------------------------------------------------------
// Phase 0: per-neuron constants
// ---------------------------------------------------------------------------
__global__ void prep_kernel(const float* __restrict__ b_in,
                            const float* __restrict__ b_rec,
                            const float* __restrict__ tau_n) {
    int h = threadIdx.x;
    s1_buf[h] = 1.f - sigmoidf_(tau_n[h]);
    s2_buf[h] = b_in[h] + b_rec[h];
}

// ---------------------------------------------------------------------------
// Phase 1: g[b*S+t][h] = (1-beta_h) * (x@W_in^T + b_in + b_rec)   (bf16 out)
// C[M=32768, N=1024] = X[M,256] * W_in[N,256]^T via mma.sync bf16.
// Tile: BM=128, BN=128, BK=32, 8 warps (each 64x32), padded smem rows (40 bf16)
// for conflict-free fragment LDS.
// ---------------------------------------------------------------------------
#define BM 128
#define BN 128
#define BK 32
#define PAD 40

__global__ __launch_bounds__(256)
void ff_gemm_kernel(const float* __restrict__ X, const float* __restrict__ W) {
    __shared__ __nv_bfloat16 As[2][BM][PAD];
    __shared__ __nv_bfloat16 Bs[2][BN][PAD];
    __shared__ float s1s[BN], s2s[BN];

    int tid = threadIdx.x;
    int nt = blockIdx.x & 7;       // 8 N tiles
    int mt = blockIdx.x >> 3;      // 256 M tiles
    int m0 = mt * BM, n0 = nt * BN;

    if (tid < BN) { s1s[tid] = s1_buf[n0 + tid]; s2s[tid] = s2_buf[n0 + tid]; }

    int lane = tid & 31, warp = tid >> 5;
    int wm = (warp >> 2) * 64;   // 0 or 64
    int wn = (warp & 3) * 32;    // 0..96

    float acc[4][4][4];
#pragma unroll
    for (int i = 0; i < 4; i++)
#pragma unroll
        for (int j = 0; j < 4; j++)
#pragma unroll
            for (int r = 0; r < 4; r++) acc[i][j][r] = 0.f;

    float4 xr[4], wrg[4];
    // load kt=0 tile
#pragma unroll
    for (int i = 0; i < 4; i++) {
        int idx = tid + i * 256; int row = idx >> 3; int c = idx & 7;
        xr[i]  = *(const float4*)(X + (size_t)(m0 + row) * I_ + c * 4);
        wrg[i] = *(const float4*)(W + (size_t)(n0 + row) * I_ + c * 4);
    }
#pragma unroll
    for (int i = 0; i < 4; i++) {
        int idx = tid + i * 256; int row = idx >> 3; int c = idx & 7;
        *(__nv_bfloat162*)&As[0][row][c * 4]     = __floats2bfloat162_rn(xr[i].x, xr[i].y);
        *(__nv_bfloat162*)&As[0][row][c * 4 + 2] = __floats2bfloat162_rn(xr[i].z, xr[i].w);
        *(__nv_bfloat162*)&Bs[0][row][c * 4]     = __floats2bfloat162_rn(wrg[i].x, wrg[i].y);
        *(__nv_bfloat162*)&Bs[0][row][c * 4 + 2] = __floats2bfloat162_rn(wrg[i].z, wrg[i].w);
    }
    __syncthreads();

    for (int kt = 0; kt < 8; kt++) {
        int buf = kt & 1;
        if (kt < 7) {
            int k0 = (kt + 1) * BK;
#pragma unroll
            for (int i = 0; i < 4; i++) {
                int idx = tid + i * 256; int row = idx >> 3; int c = idx & 7;
                xr[i]  = *(const float4*)(X + (size_t)(m0 + row) * I_ + k0 + c * 4);
                wrg[i] = *(const float4*)(W + (size_t)(n0 + row) * I_ + k0 + c * 4);
            }
        }
        // compute on current buffer (overlaps with in-flight LDGs)
#pragma unroll
        for (int ks = 0; ks < 2; ks++) {
            unsigned afr[4][4], bfr[4][2];
            int r = lane >> 2, c2 = (lane & 3) * 2;
#pragma unroll
            for (int mi = 0; mi < 4; mi++) {
                int rb = wm + mi * 16;
                afr[mi][0] = *(const unsigned*)&As[buf][rb + r    ][ks * 16 + c2];
                afr[mi][1] = *(const unsigned*)&As[buf][rb + r + 8][ks * 16 + c2];
                afr[mi][2] = *(const unsigned*)&As[buf][rb + r    ][ks * 16 + c2 + 8];
                afr[mi][3] = *(const unsigned*)&As[buf][rb + r + 8][ks * 16 + c2 + 8];
            }
#pragma unroll
            for (int ni = 0; ni < 4; ni++) {
                int cb = wn + ni * 8 + (lane >> 2);
                bfr[ni][0] = *(const unsigned*)&Bs[buf][cb][ks * 16 + (lane & 3) * 2];
                bfr[ni][1] = *(const unsigned*)&Bs[buf][cb][ks * 16 + (lane & 3) * 2 + 8];
            }
#pragma unroll
            for (int mi = 0; mi < 4; mi++)
#pragma unroll
                for (int ni = 0; ni < 4; ni++) {
                    asm volatile(
                        "mma.sync.aligned.m16n8k16.row.col.f32.bf16.bf16.f32 "
                        "{%0,%1,%2,%3}, {%4,%5,%6,%7}, {%8,%9}, {%0,%1,%2,%3};"
                        : "+f"(acc[mi][ni][0]), "+f"(acc[mi][ni][1]),
                          "+f"(acc[mi][ni][2]), "+f"(acc[mi][ni][3])
                        : "r"(afr[mi][0]), "r"(afr[mi][1]), "r"(afr[mi][2]), "r"(afr[mi][3]),
                          "r"(bfr[ni][0]), "r"(bfr[ni][1]));
                }
        }
        if (kt < 7) {
            int nb = buf ^ 1;   // safe: nb was last read in iter kt-1, barrier passed
#pragma unroll
            for (int i = 0; i < 4; i++) {
                int idx = tid + i * 256; int row = idx >> 3; int c = idx & 7;
                *(__nv_bfloat162*)&As[nb][row][c * 4]     = __floats2bfloat162_rn(xr[i].x, xr[i].y);
                *(__nv_bfloat162*)&As[nb][row][c * 4 + 2] = __floats2bfloat162_rn(xr[i].z, xr[i].w);
                *(__nv_bfloat162*)&Bs[nb][row][c * 4]     = __floats2bfloat162_rn(wrg[i].x, wrg[i].y);
                *(__nv_bfloat162*)&Bs[nb][row][c * 4 + 2] = __floats2bfloat162_rn(wrg[i].z, wrg[i].w);
            }
        }
        __syncthreads();
    }

    // Epilogue: g = (1-beta)*(c + b_in + b_rec), store bf16
    int r = lane >> 2, c2 = (lane & 3) * 2;
#pragma unroll
    for (int mi = 0; mi < 4; mi++) {
#pragma unroll
        for (int ni = 0; ni < 4; ni++) {
            int nloc = wn + ni * 8 + c2;
            int n = n0 + nloc;
            float s1a = s1s[nloc], s1b = s1s[nloc + 1];
            float s2a = s2s[nloc], s2b = s2s[nloc + 1];
            int ma = m0 + wm + mi * 16 + r;
            *(__nv_bfloat162*)&g_buf[(size_t)ma * H_ + n] =
                __floats2bfloat162_rn(s1a * (acc[mi][ni][0] + s2a), s1b * (acc[mi][ni][1] + s2b));
            *(__nv_bfloat162*)&g_buf[(size_t)(ma + 8) * H_ + n] =
                __floats2bfloat162_rn(s1a * (acc[mi][ni][2] + s2a), s1b * (acc[mi][ni][3] + s2b));
        }
    }
}

// ---------------------------------------------------------------------------
// Phase 2: sequential scan. One CTA per batch, one thread per neuron.
// Per step: d = beta*d + g + (1-beta)*rec ; mem = alpha*mem + (1-alpha)*d ;
// spike = mem>1 ; mem reset ; store spike bitmask ; __syncthreads_or for "any".
// rec is a sparse gather of W_rec columns (empty in the common case).
// g prefetched 8 steps ahead in a register ring.
// ---------------------------------------------------------------------------
__global__ __launch_bounds__(1024, 1)
void scan_kernel(const float* __restrict__ tau_m, const float* __restrict__ tau_n,
                 const float* __restrict__ W_rec) {
    int b = blockIdx.x;
    int h = threadIdx.x;
    float alpha = sigmoidf_(tau_m[h]);
    float beta  = sigmoidf_(tau_n[h]);
    float a1 = 1.f - alpha;
    float s1 = 1.f - beta;
    const __nv_bfloat16* gp = g_buf + (size_t)b * S_ * H_ + h;
    unsigned* spkrow = spk_buf + (size_t)b * S_ * 32;
    const float* wr = W_rec + (size_t)h * H_;

    float mem = 0.f, d = 0.f;
    __nv_bfloat16 ring[8];
#pragma unroll
    for (int i = 0; i < 8; i++) ring[i] = gp[(size_t)i * H_];

    int any = 0;
#pragma unroll 8
    for (int t = 0; t < S_; t++) {
        float rec = 0.f;
        if (any) {  // rare: gather active W_rec columns from prev-step bitmask
            const unsigned* mrow = spkrow + (t - 1) * 32;
            for (int w = 0; w < 32; w++) {
                unsigned msk = mrow[w];
                while (msk) {
                    int j = __ffs((int)msk) - 1;
                    rec += wr[w * 32 + j];
                    msk &= msk - 1;
                }
            }
        }
        float gv = __bfloat162float(ring[t & 7]);
        if (t + 8 < S_) ring[t & 7] = gp[(size_t)(t + 8) * H_];

        d = fmaf(beta, d, fmaf(s1, rec, gv));
        mem = fmaf(alpha, mem, a1 * d);
        int spike = mem > 1.0f;
        if (spike) mem = 0.f;

        unsigned bal = __ballot_sync(0xffffffffu, spike);
        if ((h & 31) == 0) spkrow[t * 32 + (h >> 5)] = bal;
        any = __syncthreads_or(spike);   // barrier + block-OR + mem fence
    }
}

// ---------------------------------------------------------------------------
// Phase 3: out[b,t,:] = sigmoid(spike @ W_out^T + b_out). One warp per (b,t).
// Fast path (no spikes): broadcast precomputed sigmoid(b_out).
// ---------------------------------------------------------------------------
__global__ __launch_bounds__(256)
void out_kernel(const float* __restrict__ W_out, const float* __restrict__ b_out,
                float* __restrict__ out) {
    __shared__ float sig[O_];
    int tid = threadIdx.x;
    if (tid < O_) sig[tid] = sigmoidf_(b_out[tid]);
    __syncthreads();

    int warp = tid >> 5, lane = tid & 31;
    int row = blockIdx.x * 8 + warp;           // 4096 blocks * 8 warps = 32768 rows
    const unsigned* mrow = spk_buf + (size_t)row * 32;
    unsigned w = mrow[lane];
    unsigned anyb = __ballot_sync(0xffffffffu, w != 0);
    float* orow = out + (size_t)row * O_;
    if (!anyb) {
        float4 v = *(const float4*)&sig[lane * 4];
        *(float4*)&orow[lane * 4] = v;
    } else {
        float acc0 = b_out[lane * 4 + 0], acc1 = b_out[lane * 4 + 1];
        float acc2 = b_out[lane * 4 + 2], acc3 = b_out[lane * 4 + 3];
        for (int ww = 0; ww < 32; ww++) {
            unsigned m = __shfl_sync(0xffffffffu, w, ww);
            while (m) {
                int j = ww * 32 + __ffs((int)m) - 1;
                m &= m - 1;
                const float* wo = W_out + j;           // W_out[o*H + j]
                acc0 += wo[(size_t)(lane * 4 + 0) * H_];
                acc1 += wo[(size_t)(lane * 4 + 1) * H_];
                acc2 += wo[(size_t)(lane * 4 + 2) * H_];
                acc3 += wo[(size_t)(lane * 4 + 3) * H_];
            }
        }
        orow[lane * 4 + 0] = sigmoidf_(acc0);
        orow[lane * 4 + 1] = sigmoidf_(acc1);
        orow[lane * 4 + 2] = sigmoidf_(acc2);
        orow[lane * 4 + 3] = sigmoidf_(acc3);
    }
}

// ---------------------------------------------------------------------------
extern "C" void kernel_launch(void* const* d_in, const int* in_sizes, int n_in,
                              void* d_out, int out_size) {
    const float* x     = (const float*)d_in[0];
    const float* W_in  = (const float*)d_in[1];
    const float* b_in  = (const float*)d_in[2];
    const float* W_rec = (const float*)d_in[3];
    const float* b_rec = (const float*)d_in[4];
    const float* tau_m = (const float*)d_in[5];
    const float* tau_n = (const float*)d_in[6];
    const float* W_out = (const float*)d_in[7];
    const float* b_out = (const float*)d_in[8];
    float* out = (float*)d_out;

    prep_kernel<<<1, H_>>>(b_in, b_rec, tau_n);
    ff_gemm_kernel<<<(B_ * S_ / BM) * (H_ / BN), 256>>>(x, W_in);
    scan_kernel<<<B_, H_>>>(tau_m, tau_n, W_rec);
    out_kernel<<<B_ * S_ / 8, 256>>>(W_out, b_out, out);
}

// round 6
// speedup vs baseline: 1.7317x; 1.7317x over previous
#include <cuda_runtime.h>
#include <cuda_bf16.h>
#include <math.h>
#include <stdint.h>

#define B_ 64
#define S_ 512
#define I_ 256
#define H_ 1024
#define O_ 128

// ---------------- static device scratch (no dynamic allocation) ------------
__device__ __nv_bfloat16 g_buf[((size_t)B_ * S_ + 16) * H_]; // g2=(1-a)(1-b)(ff+bias), bf16 (+16 rows prefetch pad)
__device__ __nv_bfloat16 xbf[(size_t)B_ * S_ * I_];          // x in bf16
__device__ __nv_bfloat16 wbf[(size_t)H_ * I_];               // W_in in bf16
__device__ unsigned      spk_buf[(size_t)B_ * S_ * (H_ / 32)];
__device__ unsigned char rowflag[(size_t)B_ * S_];
__device__ float         s1_buf[H_];                          // (1-alpha)(1-beta)
__device__ float         s2_buf[H_];                          // b_in + b_rec

__device__ __forceinline__ float sigmoidf_(float x) { return 1.f / (1.f + expf(-x)); }

__device__ __forceinline__ uint32_t smem_u32(const void* p) {
    uint32_t a;
    asm("{ .reg .u64 t; cvta.to.shared.u64 t, %1; cvt.u32.u64 %0, t; }" : "=r"(a) : "l"(p));
    return a;
}
__device__ __forceinline__ void cp_async16(uint32_t dst, const void* src) {
    asm volatile("cp.async.cg.shared.global [%0], [%1], 16;" :: "r"(dst), "l"(src) : "memory");
}
__device__ __forceinline__ void cp_commit() {
    asm volatile("cp.async.commit_group;" ::: "memory");
}

// ---------------------------------------------------------------------------
// Phase 0a: convert W_in to bf16; per-neuron constants.
// ---------------------------------------------------------------------------
__global__ void prep_kernel(const float* __restrict__ W_in, const float* __restrict__ b_in,
                            const float* __restrict__ b_rec, const float* __restrict__ tau_m,
                            const float* __restrict__ tau_n) {
    int idx = blockIdx.x * 1024 + threadIdx.x;   // 256 blocks cover 262144
    wbf[idx] = __float2bfloat16(W_in[idx]);
    if (blockIdx.x == 0) {
        int h = threadIdx.x;
        float a1 = 1.f - sigmoidf_(tau_m[h]);
        float b1 = 1.f - sigmoidf_(tau_n[h]);
        s1_buf[h] = a1 * b1;
        s2_buf[h] = b_in[h] + b_rec[h];
    }
}

// ---------------------------------------------------------------------------
// Phase 0b: convert x to bf16 (vectorized).
// ---------------------------------------------------------------------------
__global__ void xcvt_kernel(const float* __restrict__ x) {
    size_t i = (size_t)blockIdx.x * 1024 + threadIdx.x;   // 2048*1024 float4s
    float4 v = ((const float4*)x)[i];
    __nv_bfloat162 a = __floats2bfloat162_rn(v.x, v.y);
    __nv_bfloat162 b = __floats2bfloat162_rn(v.z, v.w);
    ((uint2*)xbf)[i] = make_uint2(*(unsigned*)&a, *(unsigned*)&b);
}

// ---------------------------------------------------------------------------
// Phase 1: HMMA GEMM. g[m][n] = s1[n]*(X[m,:]·W[n,:] + s2[n]), bf16 out.
// C[32768,1024] = Xbf[32768,256] @ Wbf[1024,256]^T.
// BM=BN=128, BK=32, 8 warps (64x32 each), 3-stage cp.async pipeline,
// padded smem rows (40 bf16) for conflict-tolerable fragment LDS.
// ---------------------------------------------------------------------------
#define BK 32
#define PAD 40
#define STG_BYTES (128 * PAD * 2)          // 10240 B per stage per matrix
#define SM_AS 0
#define SM_BS (3 * STG_BYTES)              // 30720
#define SM_S12 (6 * STG_BYTES)             // 61440
#define SMEM_BYTES (SM_S12 + 128 * 8)      // 62464

__global__ __launch_bounds__(256, 2)
void ff_gemm_kernel() {
    extern __shared__ char smem[];
    uint32_t sa = smem_u32(smem) + SM_AS;
    uint32_t sbm = smem_u32(smem) + SM_BS;
    float2* s12 = (float2*)(smem + SM_S12);

    int tid = threadIdx.x, lane = tid & 31, warp = tid >> 5;
    int nt = blockIdx.x & 7, mt = blockIdx.x >> 3;
    int m0 = mt * 128, n0 = nt * 128;

    if (tid < 128) s12[tid] = make_float2(s1_buf[n0 + tid], s2_buf[n0 + tid]);

    // per-thread load slots: 512 16B chunks per tile per matrix, 2 each
    int r0 = (tid * 2) >> 2, c0 = (tid * 2) & 3;
    int r1 = (tid * 2 + 1) >> 2, c1 = (tid * 2 + 1) & 3;
    const __nv_bfloat16* Abase = xbf + (size_t)m0 * I_;
    const __nv_bfloat16* Bbase = wbf + (size_t)n0 * I_;

#define ISSUE(kt) do {                                                          \
        int st = (kt) % 3; int k0 = (kt) * BK;                                  \
        cp_async16(sa  + st * STG_BYTES + r0 * (PAD * 2) + c0 * 16,             \
                   Abase + (size_t)r0 * I_ + k0 + c0 * 8);                      \
        cp_async16(sa  + st * STG_BYTES + r1 * (PAD * 2) + c1 * 16,             \
                   Abase + (size_t)r1 * I_ + k0 + c1 * 8);                      \
        cp_async16(sbm + st * STG_BYTES + r0 * (PAD * 2) + c0 * 16,             \
                   Bbase + (size_t)r0 * I_ + k0 + c0 * 8);                      \
        cp_async16(sbm + st * STG_BYTES + r1 * (PAD * 2) + c1 * 16,             \
                   Bbase + (size_t)r1 * I_ + k0 + c1 * 8);                      \
        cp_commit();                                                            \
    } while (0)

    ISSUE(0);
    ISSUE(1);

    int wm = (warp >> 2) * 64;   // 0 or 64
    int wn = (warp & 3) * 32;    // 0..96
    int fr = lane >> 2, fc = (lane & 3) * 2;

    float acc[4][4][4];
#pragma unroll
    for (int i = 0; i < 4; i++)
#pragma unroll
        for (int j = 0; j < 4; j++)
#pragma unroll
            for (int r = 0; r < 4; r++) acc[i][j][r] = 0.f;

    for (int kt = 0; kt < 8; kt++) {
        if (kt < 7) asm volatile("cp.async.wait_group 1;" ::: "memory");
        else        asm volatile("cp.async.wait_group 0;" ::: "memory");
        __syncthreads();
        if (kt + 2 < 8) ISSUE(kt + 2);

        uint32_t abuf = sa  + (kt % 3) * STG_BYTES;
        uint32_t bbuf = sbm + (kt % 3) * STG_BYTES;
#pragma unroll
        for (int ks = 0; ks < 2; ks++) {
            unsigned afr[4][4], bfr[4][2];
#pragma unroll
            for (int mi = 0; mi < 4; mi++) {
                int rb = wm + mi * 16;
                uint32_t base = abuf + (rb + fr) * (PAD * 2) + (ks * 16 + fc) * 2;
                asm("ld.shared.b32 %0, [%1];" : "=r"(afr[mi][0]) : "r"(base));
                asm("ld.shared.b32 %0, [%1];" : "=r"(afr[mi][1]) : "r"(base + 8 * PAD * 2));
                asm("ld.shared.b32 %0, [%1];" : "=r"(afr[mi][2]) : "r"(base + 16));
                asm("ld.shared.b32 %0, [%1];" : "=r"(afr[mi][3]) : "r"(base + 8 * PAD * 2 + 16));
            }
#pragma unroll
            for (int ni = 0; ni < 4; ni++) {
                int cb = wn + ni * 8 + fr;
                uint32_t base = bbuf + cb * (PAD * 2) + (ks * 16 + fc) * 2;
                asm("ld.shared.b32 %0, [%1];" : "=r"(bfr[ni][0]) : "r"(base));
                asm("ld.shared.b32 %0, [%1];" : "=r"(bfr[ni][1]) : "r"(base + 16));
            }
#pragma unroll
            for (int mi = 0; mi < 4; mi++)
#pragma unroll
                for (int ni = 0; ni < 4; ni++) {
                    asm volatile(
                        "mma.sync.aligned.m16n8k16.row.col.f32.bf16.bf16.f32 "
                        "{%0,%1,%2,%3}, {%4,%5,%6,%7}, {%8,%9}, {%0,%1,%2,%3};"
                        : "+f"(acc[mi][ni][0]), "+f"(acc[mi][ni][1]),
                          "+f"(acc[mi][ni][2]), "+f"(acc[mi][ni][3])
                        : "r"(afr[mi][0]), "r"(afr[mi][1]), "r"(afr[mi][2]), "r"(afr[mi][3]),
                          "r"(bfr[ni][0]), "r"(bfr[ni][1]));
                }
        }
        __syncthreads();
    }

    // Epilogue: g = s1*(c + s2), bf16
#pragma unroll
    for (int mi = 0; mi < 4; mi++) {
#pragma unroll
        for (int ni = 0; ni < 4; ni++) {
            int nloc = wn + ni * 8 + fc;
            int n = n0 + nloc;
            float2 pa = s12[nloc], pb = s12[nloc + 1];
            int ma = m0 + wm + mi * 16 + fr;
            *(__nv_bfloat162*)&g_buf[(size_t)ma * H_ + n] =
                __floats2bfloat162_rn(pa.x * (acc[mi][ni][0] + pa.y), pb.x * (acc[mi][ni][1] + pb.y));
            *(__nv_bfloat162*)&g_buf[(size_t)(ma + 8) * H_ + n] =
                __floats2bfloat162_rn(pa.x * (acc[mi][ni][2] + pa.y), pb.x * (acc[mi][ni][3] + pb.y));
        }
    }
#undef ISSUE
}

// ---------------------------------------------------------------------------
// Phase 2: speculative chunked scan. One CTA/batch, one thread/neuron.
// D = beta*D + g2 (+ s1c*rec); mem = alpha*mem + D; spike iff mem>1.
// 64-step optimistic chunks (rec=0, no resets, track max(mem)); ONE
// __syncthreads_or per chunk. Exact replay on any detected crossing.
// ---------------------------------------------------------------------------
__global__ __launch_bounds__(1024, 1)
void scan_kernel(const float* __restrict__ tau_m, const float* __restrict__ tau_n,
                 const float* __restrict__ W_rec) {
    int b = blockIdx.x, h = threadIdx.x;
    float alpha = sigmoidf_(tau_m[h]);
    float beta  = sigmoidf_(tau_n[h]);
    float s1c = (1.f - alpha) * (1.f - beta);
    const __nv_bfloat16* gp = g_buf + (size_t)b * S_ * H_ + h;
    unsigned* spkrow = spk_buf + (size_t)b * S_ * 32;
    unsigned char* rf = rowflag + (size_t)b * S_;
    const float* wr = W_rec + (size_t)h * H_;

    float mem = 0.f, D = 0.f;
    __nv_bfloat16 ring[16];
#pragma unroll
    for (int i = 0; i < 16; i++) ring[i] = gp[(size_t)i * H_];
    const __nv_bfloat16* pf = gp + (size_t)16 * H_;   // g_buf has +16 rows pad

    int carry = 0;
    for (int chunk = 0; chunk < 8; chunk++) {
        int base = chunk * 64;
        float mem0 = mem, D0 = D, maxm = 0.f;
        for (int u = 0; u < 64; u += 16) {
#pragma unroll
            for (int v = 0; v < 16; v++) {
                float gv = __bfloat162float(ring[v]);
                ring[v] = *pf; pf += H_;
                D = fmaf(beta, D, gv);
                mem = fmaf(alpha, mem, D);
                maxm = fmaxf(maxm, mem);
            }
        }
        int any = __syncthreads_or(maxm > 1.f);
        if (!(any | carry)) {
            if (h < 64) rf[base + h] = 0;
            carry = 0;
        } else {
            // exact replay of this chunk
            mem = mem0; D = D0;
            int prev = carry;
            for (int tt = 0; tt < 64; tt++) {
                int t = base + tt;
                float rec = 0.f;
                if (prev) {
                    const unsigned* mrow = spkrow + (size_t)(t - 1) * 32;
                    for (int w2 = 0; w2 < 32; w2++) {
                        unsigned msk = mrow[w2];
                        while (msk) {
                            int j = __ffs((int)msk) - 1;
                            rec += wr[w2 * 32 + j];
                            msk &= msk - 1;
                        }
                    }
                }
                float gv = __bfloat162float(gp[(size_t)t * H_]);
                D = fmaf(beta, D, fmaf(s1c, rec, gv));
                mem = fmaf(alpha, mem, D);
                int spike = mem > 1.f;
                if (spike) mem = 0.f;
                unsigned bal = __ballot_sync(0xffffffffu, spike);
                if ((h & 31) == 0) spkrow[(size_t)t * 32 + (h >> 5)] = bal;
                prev = __syncthreads_or(spike);
                if (h == 0) rf[t] = (unsigned char)prev;
            }
            carry = prev;
        }
    }
}

// ---------------------------------------------------------------------------
// Phase 3: out[b,t,:] = sigmoid(spike @ W_out^T + b_out). One warp per row.
// rowflag==0 fast path: broadcast precomputed sigmoid(b_out), no mask reads.
// ---------------------------------------------------------------------------
__global__ __launch_bounds__(256)
void out_kernel(const float* __restrict__ W_out, const float* __restrict__ b_out,
                float* __restrict__ out) {
    __shared__ float sig[O_];
    int tid = threadIdx.x;
    if (tid < O_) sig[tid] = sigmoidf_(b_out[tid]);
    __syncthreads();

    int warp = tid >> 5, lane = tid & 31;
    int row = blockIdx.x * 8 + warp;
    float* orow = out + (size_t)row * O_;
    if (!rowflag[row]) {
        *(float4*)(orow + lane * 4) = *(const float4*)&sig[lane * 4];
    } else {
        const unsigned* mrow = spk_buf + (size_t)row * 32;
        unsigned w = mrow[lane];
        float acc0 = b_out[lane * 4 + 0], acc1 = b_out[lane * 4 + 1];
        float acc2 = b_out[lane * 4 + 2], acc3 = b_out[lane * 4 + 3];
        for (int ww = 0; ww < 32; ww++) {
            unsigned m = __shfl_sync(0xffffffffu, w, ww);
            while (m) {
                int j = ww * 32 + __ffs((int)m) - 1;
                m &= m - 1;
                const float* wo = W_out + j;
                acc0 += wo[(size_t)(lane * 4 + 0) * H_];
                acc1 += wo[(size_t)(lane * 4 + 1) * H_];
                acc2 += wo[(size_t)(lane * 4 + 2) * H_];
                acc3 += wo[(size_t)(lane * 4 + 3) * H_];
            }
        }
        orow[lane * 4 + 0] = sigmoidf_(acc0);
        orow[lane * 4 + 1] = sigmoidf_(acc1);
        orow[lane * 4 + 2] = sigmoidf_(acc2);
        orow[lane * 4 + 3] = sigmoidf_(acc3);
    }
}

// ---------------------------------------------------------------------------
extern "C" void kernel_launch(void* const* d_in, const int* in_sizes, int n_in,
                              void* d_out, int out_size) {
    const float* x     = (const float*)d_in[0];
    const float* W_in  = (const float*)d_in[1];
    const float* b_in  = (const float*)d_in[2];
    const float* W_rec = (const float*)d_in[3];
    const float* b_rec = (const float*)d_in[4];
    const float* tau_m = (const float*)d_in[5];
    const float* tau_n = (const float*)d_in[6];
    const float* W_out = (const float*)d_in[7];
    const float* b_out = (const float*)d_in[8];
    float* out = (float*)d_out;

    static int attr_done = 0;
    if (!attr_done) {
        cudaFuncSetAttribute(ff_gemm_kernel, cudaFuncAttributeMaxDynamicSharedMemorySize, SMEM_BYTES);
        attr_done = 1;
    }

    prep_kernel<<<256, 1024>>>(W_in, b_in, b_rec, tau_m, tau_n);
    xcvt_kernel<<<2048, 1024>>>(x);
    ff_gemm_kernel<<<2048, 256, SMEM_BYTES>>>();
    scan_kernel<<<64, 1024>>>(tau_m, tau_n, W_rec);
    out_kernel<<<B_ * S_ / 8, 256>>>(W_out, b_out, out);
}